// round 15
// baseline (speedup 1.0000x reference)
#include <cuda_runtime.h>
#include <cuda_bf16.h>
#include <cuda_fp16.h>
#include <stdint.h>

#define D 128
#define MAXN 50048
#define MAXE 600064
#define BN_EPS 1e-5f
#define MAXCHUNKS 128

// ---------------- scratch (no allocation allowed) ----------------
__device__ float  g_h  [(size_t)MAXN * D];  // x@W_mlp (raw, pre-BN)
__device__ __half g_hch[(size_t)MAXN * D];  // relu(bn1(h)) @ W_conv, fp16 (gather-only)
__device__ float  g_acc[(size_t)MAXN * D];  // GCN aggregation result
__device__ int    g_degi[MAXN];
__device__ float  g_dinv[MAXN];
__device__ int    g_coff[MAXN + 1];
__device__ int    g_cursor[MAXN];
__device__ int    g_csr[MAXE];
__device__ int    g_part[MAXCHUNKS];
__device__ int    g_pbase[MAXCHUNKS];
__device__ float  g_sum1[D], g_sq1[D], g_sum2[D], g_sq2[D];
__device__ float  g_a1[D], g_c1[D];
__device__ int    g_ctr[4];                 // phase counters (reset in k_pack)
__device__ uint32_t g_Bph[2][64 * D];       // packed bf16 hi planes
__device__ uint32_t g_Bpl[2][64 * D];       // packed bf16 lo planes

// ---------------- bf16 split helpers ----------------
__device__ __forceinline__ void split_bf16(float v, float& hi, float& lo) {
    __nv_bfloat16 h = __float2bfloat16_rn(v);
    hi = __bfloat162float(h);
    lo = v - hi;
}
__device__ __forceinline__ uint32_t pack_bf16x2(float a, float b) {
    __nv_bfloat162 p = __floats2bfloat162_rn(a, b);
    return *reinterpret_cast<uint32_t*>(&p);
}
__device__ __forceinline__ void mma_bf16(float* c, const uint32_t* a,
                                         uint32_t b0, uint32_t b1) {
    asm volatile(
        "mma.sync.aligned.m16n8k16.row.col.f32.bf16.bf16.f32 "
        "{%0,%1,%2,%3}, {%4,%5,%6,%7}, {%8,%9}, {%0,%1,%2,%3};"
        : "+f"(c[0]), "+f"(c[1]), "+f"(c[2]), "+f"(c[3])
        : "r"(a[0]), "r"(a[1]), "r"(a[2]), "r"(a[3]), "r"(b0), "r"(b1));
}

// ---------------- pack weights + reset ALL cross-call state -----------------
__global__ void k_pack(const float* __restrict__ Wm, const float* __restrict__ Wc,
                       int N) {
    if (blockIdx.x == 0) {
        if (threadIdx.x < 4) g_ctr[threadIdx.x] = 0;
        if (threadIdx.x < D) {
            g_sum1[threadIdx.x] = 0.f; g_sq1[threadIdx.x] = 0.f;
            g_sum2[threadIdx.x] = 0.f; g_sq2[threadIdx.x] = 0.f;
        }
    }
    for (int i = blockIdx.x * 256 + threadIdx.x; i < N; i += gridDim.x * 256)
        g_degi[i] = 0;

    int idx = blockIdx.x * blockDim.x + threadIdx.x;   // 0..16383
    if (idx < 2 * 64 * D) {
        int m = idx >> 13;
        int rest = idx & 8191;         // k2*128 + col
        int k2 = rest >> 7, col = rest & 127;
        const float* W = (m == 0) ? Wm : Wc;
        float v0 = W[(2 * k2) * D + col];
        float v1 = W[(2 * k2 + 1) * D + col];
        float h0, l0, h1, l1;
        split_bf16(v0, h0, l0);
        split_bf16(v1, h1, l1);
        g_Bph[m][rest] = pack_bf16x2(h0, h1);
        g_Bpl[m][rest] = pack_bf16x2(l0, l1);
    }
}

// ---------------- bf16x3 MMA GEMM body ----------------
// MODE 0: A=x -> g_h (fp32). MODE 1: A=g_h + BN1 affine + ReLU -> g_hch (fp16).
#define APST 12
#define BPST 136
template <int MODE>
__device__ __forceinline__ void gemm_body(const float* __restrict__ Ain, int M, int blk) {
    __shared__ __align__(16) uint32_t Ahp[2][128 * APST], Alp[2][128 * APST];
    __shared__ __align__(16) uint32_t Bhp[2][8 * BPST],   Blp[2][8 * BPST];
    const float* A = (MODE == 0) ? Ain : g_h;

    const int tid  = threadIdx.x;
    const int w    = tid >> 5;
    const int lane = tid & 31;
    const int g    = lane >> 2;
    const int t    = lane & 3;
    const int row0 = blk * 128;

    const int r0_ = tid >> 2,         c40 = tid & 3;
    const int r1_ = (tid + 256) >> 2, c41 = (tid + 256) & 3;
    const int gr0 = row0 + r0_, gr1 = row0 + r1_;

    float acc[16][4];
    #pragma unroll
    for (int n = 0; n < 16; n++)
        #pragma unroll
        for (int i = 0; i < 4; i++) acc[n][i] = 0.f;

    auto loadA = [&](int kk, float4& v0, float4& v1) {
        v0 = make_float4(0.f, 0.f, 0.f, 0.f);
        v1 = make_float4(0.f, 0.f, 0.f, 0.f);
        if (gr0 < M) v0 = *(const float4*)(A + (size_t)gr0 * D + kk + c40 * 4);
        if (gr1 < M) v1 = *(const float4*)(A + (size_t)gr1 * D + kk + c41 * 4);
    };
    auto convertA = [&](int kk, int buf, float4 v0, float4 v1) {
        #pragma unroll
        for (int i = 0; i < 2; i++) {
            float4 v = i ? v1 : v0;
            int r = i ? r1_ : r0_;
            int c4 = i ? c41 : c40;
            if (MODE == 1) {
                int c = kk + c4 * 4;
                v.x = fmaxf(fmaf(v.x, g_a1[c + 0], g_c1[c + 0]), 0.f);
                v.y = fmaxf(fmaf(v.y, g_a1[c + 1], g_c1[c + 1]), 0.f);
                v.z = fmaxf(fmaf(v.z, g_a1[c + 2], g_c1[c + 2]), 0.f);
                v.w = fmaxf(fmaf(v.w, g_a1[c + 3], g_c1[c + 3]), 0.f);
            }
            float hx, lx, hy, ly, hz, lz, hw, lw;
            split_bf16(v.x, hx, lx); split_bf16(v.y, hy, ly);
            split_bf16(v.z, hz, lz); split_bf16(v.w, hw, lw);
            uint32_t* ph = &Ahp[buf][r * APST + c4 * 2];
            uint32_t* pl = &Alp[buf][r * APST + c4 * 2];
            ph[0] = pack_bf16x2(hx, hy); ph[1] = pack_bf16x2(hz, hw);
            pl[0] = pack_bf16x2(lx, ly); pl[1] = pack_bf16x2(lz, lw);
        }
    };
    auto issueB = [&](int c, int buf) {
        int k2l = tid >> 5, c4 = tid & 31;
        int srcw = (c * 8 + k2l) * D + c4 * 4;
        uint32_t dh = (uint32_t)__cvta_generic_to_shared(&Bhp[buf][k2l * BPST + c4 * 4]);
        uint32_t dl = (uint32_t)__cvta_generic_to_shared(&Blp[buf][k2l * BPST + c4 * 4]);
        asm volatile("cp.async.cg.shared.global [%0], [%1], 16;\n"
                     :: "r"(dh), "l"(&g_Bph[MODE][srcw]));
        asm volatile("cp.async.cg.shared.global [%0], [%1], 16;\n"
                     :: "r"(dl), "l"(&g_Bpl[MODE][srcw]));
        asm volatile("cp.async.commit_group;\n");
    };

    {
        float4 v0, v1;
        loadA(0, v0, v1);
        issueB(0, 0);
        convertA(0, 0, v0, v1);
        asm volatile("cp.async.wait_group 0;\n");
    }
    __syncthreads();

    for (int c = 0; c < 8; c++) {
        const int buf = c & 1, nb = buf ^ 1;
        const int kk = c * 16;
        float4 v0, v1;
        if (c < 7) {
            loadA(kk + 16, v0, v1);
            issueB(c + 1, nb);
        }

        uint32_t ah[4], al[4];
        {
            int ra = (w * 16 + g) * APST + t;
            int rb = (w * 16 + g + 8) * APST + t;
            ah[0] = Ahp[buf][ra];     ah[1] = Ahp[buf][rb];
            ah[2] = Ahp[buf][ra + 4]; ah[3] = Ahp[buf][rb + 4];
            al[0] = Alp[buf][ra];     al[1] = Alp[buf][rb];
            al[2] = Alp[buf][ra + 4]; al[3] = Alp[buf][rb + 4];
        }
        #pragma unroll
        for (int nt = 0; nt < 16; nt++) {
            int bi = t * BPST + nt * 8 + g;
            uint32_t bh0 = Bhp[buf][bi], bh1 = Bhp[buf][bi + 4 * BPST];
            uint32_t bl0 = Blp[buf][bi], bl1 = Blp[buf][bi + 4 * BPST];
            mma_bf16(acc[nt], ah, bh0, bh1);
            mma_bf16(acc[nt], ah, bl0, bl1);
            mma_bf16(acc[nt], al, bh0, bh1);
        }

        if (c < 7) {
            convertA(kk + 16, nb, v0, v1);
            asm volatile("cp.async.wait_group 0;\n");
            __syncthreads();
        }
    }

    int rA = row0 + w * 16 + g;
    int rB = rA + 8;
    #pragma unroll
    for (int nt = 0; nt < 16; nt++) {
        int col = nt * 8 + 2 * t;
        if (MODE == 0) {
            if (rA < M)
                *(float2*)(g_h + (size_t)rA * D + col) = make_float2(acc[nt][0], acc[nt][1]);
            if (rB < M)
                *(float2*)(g_h + (size_t)rB * D + col) = make_float2(acc[nt][2], acc[nt][3]);
        } else {
            if (rA < M)
                *(__half2*)(g_hch + (size_t)rA * D + col) =
                    __floats2half2_rn(acc[nt][0], acc[nt][1]);
            if (rB < M)
                *(__half2*)(g_hch + (size_t)rB * D + col) =
                    __floats2half2_rn(acc[nt][2], acc[nt][3]);
        }
    }
}

// ---------------- merged kernel 2: gemm0 + degree histogram -----------------
__global__ void __launch_bounds__(256, 2) k_g0(const float* __restrict__ x,
                                               const int* __restrict__ dst,
                                               int E, int N, int GB) {
    if ((int)blockIdx.x < GB) {
        gemm_body<0>(x, N, blockIdx.x);
    } else {
        int e = (blockIdx.x - GB) * 256 + threadIdx.x;
        if (e < E) {
            int d = dst[e];
            if ((unsigned)d < (unsigned)N) atomicAdd(&g_degi[d], 1);
        }
    }
}

// ---------------- merged kernel 3: colstats0(+BN1 affine) + scan1/2 ---------
__global__ void k_cs0s1(int N, const float* __restrict__ gam1,
                        const float* __restrict__ bet1, float invN, int nchunks) {
    if (blockIdx.x < 256) {
        // ---- colstats0 over g_h; last block computes BN1 affine ----
        __shared__ __align__(16) float ss[8][D], sr[8][D];
        __shared__ int lastblk;
        int tid = threadIdx.x;
        int wid = tid >> 5, lane = tid & 31;
        float4 s = make_float4(0.f, 0.f, 0.f, 0.f);
        float4 q = make_float4(0.f, 0.f, 0.f, 0.f);
        for (int r = blockIdx.x * 8 + wid; r < N; r += 256 * 8) {
            float4 v = ((const float4*)(g_h + (size_t)r * D))[lane];
            s.x += v.x; s.y += v.y; s.z += v.z; s.w += v.w;
            q.x += v.x * v.x; q.y += v.y * v.y; q.z += v.z * v.z; q.w += v.w * v.w;
        }
        ((float4*)ss[wid])[lane] = s;
        ((float4*)sr[wid])[lane] = q;
        __syncthreads();
        if (tid < D) {
            float a = 0.f, b = 0.f;
            #pragma unroll
            for (int wv = 0; wv < 8; wv++) { a += ss[wv][tid]; b += sr[wv][tid]; }
            atomicAdd(&g_sum1[tid], a);
            atomicAdd(&g_sq1[tid], b);
        }
        __threadfence();
        __syncthreads();
        if (tid == 0) {
            int ret = atomicAdd(&g_ctr[0], 1);
            lastblk = (ret == 255);
        }
        __syncthreads();
        if (lastblk && tid < D) {
            float mean = __ldcg(&g_sum1[tid]) * invN;
            float var  = __ldcg(&g_sq1[tid]) * invN - mean * mean;
            float sc = gam1[tid] * rsqrtf(var + BN_EPS);
            g_a1[tid] = sc;
            g_c1[tid] = bet1[tid] - mean * sc;
        }
        return;
    }
    // ---- scan1: per-chunk degree sums; phase 2 in last block ----
    __shared__ int red[256];
    __shared__ int lastblk1;
    int chunk = blockIdx.x - 256;
    int tid = threadIdx.x;
    int i0 = chunk * 512 + 2 * tid;
    int d0 = (i0 < N) ? g_degi[i0] : 0;
    int d1 = (i0 + 1 < N) ? g_degi[i0 + 1] : 0;
    red[tid] = d0 + d1;
    __syncthreads();
    #pragma unroll
    for (int off = 128; off > 0; off >>= 1) {
        if (tid < off) red[tid] += red[tid + off];
        __syncthreads();
    }
    if (tid == 0) g_part[chunk] = red[0];
    __threadfence();
    __syncthreads();
    if (tid == 0) {
        int ret = atomicAdd(&g_ctr[2], 1);
        lastblk1 = (ret == nchunks - 1);
    }
    __syncthreads();
    if (!lastblk1) return;

    __shared__ int s[MAXCHUNKS];
    if (tid < MAXCHUNKS)
        s[tid] = (tid < nchunks) ? __ldcg(&g_part[tid]) : 0;
    __syncthreads();
    #pragma unroll
    for (int off = 1; off < MAXCHUNKS; off <<= 1) {
        int v = 0, u = 0;
        if (tid < MAXCHUNKS) { v = s[tid]; u = (tid >= off) ? s[tid - off] : 0; }
        __syncthreads();
        if (tid < MAXCHUNKS) s[tid] = v + u;
        __syncthreads();
    }
    if (tid < nchunks) g_pbase[tid] = (tid > 0) ? s[tid - 1] : 0;
}

// ---------------- merged kernel 4: gemm1 + scan3 + CSR fill -----------------
__global__ void __launch_bounds__(256, 2) k_g1s3f(const int* __restrict__ src,
                                                  const int* __restrict__ dst,
                                                  int E, int N, int GB, int nchunks) {
    if ((int)blockIdx.x < GB) {
        gemm_body<1>(nullptr, N, blockIdx.x);
        return;
    }
    // ---- scan3: intra-chunk exclusive scan + dinv ----
    __shared__ int sp[256];
    int chunk = blockIdx.x - GB;
    int tid = threadIdx.x;
    int i0 = chunk * 512 + 2 * tid;
    int d0 = (i0 < N) ? g_degi[i0] : 0;
    int d1 = (i0 + 1 < N) ? g_degi[i0 + 1] : 0;
    int ps = d0 + d1;
    sp[tid] = ps;
    __syncthreads();
    #pragma unroll
    for (int off = 1; off < 256; off <<= 1) {
        int v = sp[tid];
        int u = (tid >= off) ? sp[tid - off] : 0;
        __syncthreads();
        sp[tid] = v + u;
        __syncthreads();
    }
    int base = g_pbase[chunk];
    int excl = base + sp[tid] - ps;
    if (i0 < N) {
        g_coff[i0] = excl;
        g_cursor[i0] = excl;
        g_dinv[i0] = rsqrtf((float)d0 + 1.0f);
        if (i0 == N - 1) g_coff[N] = excl + d0;
    }
    if (i0 + 1 < N) {
        g_coff[i0 + 1] = excl + d0;
        g_cursor[i0 + 1] = excl + d0;
        g_dinv[i0 + 1] = rsqrtf((float)d1 + 1.0f);
        if (i0 + 1 == N - 1) g_coff[N] = excl + d0 + d1;
    }
    // ---- phase sync among the nchunks scan3 blocks ----
    __threadfence();
    __syncthreads();
    if (tid == 0) {
        atomicAdd(&g_ctr[3], 1);
        while (atomicAdd(&g_ctr[3], 0) < nchunks) __nanosleep(64);
    }
    __syncthreads();
    __threadfence();
    // ---- CSR fill, distributed over the scan3 blocks (overlaps gemm1) ----
    for (int e = chunk * 256 + tid; e < E; e += nchunks * 256) {
        int d = dst[e], sidx = src[e];
        if ((unsigned)d < (unsigned)N && (unsigned)sidx < (unsigned)N) {
            int pos = atomicAdd(&g_cursor[d], 1);
            g_csr[pos] = sidx;
        }
    }
}

// ---------------- gather aggregation (fp16 rows): warp per destination ------
__global__ void k_gather(int N) {
    int w = (blockIdx.x * blockDim.x + threadIdx.x) >> 5;
    int lane = threadIdx.x & 31;
    if (w >= N) return;
    int d = w;
    int beg = g_coff[d], end = g_coff[d + 1];
    float wd = g_dinv[d];

    auto loadrow = [&](int row, float2& f0, float2& f1) {
        uint2 raw = *(const uint2*)(g_hch + (size_t)row * D + lane * 4);
        f0 = __half22float2(*(__half2*)&raw.x);
        f1 = __half22float2(*(__half2*)&raw.y);
    };

    float2 f0, f1;
    loadrow(d, f0, f1);
    float w0 = wd * wd;
    float4 acc = make_float4(w0 * f0.x, w0 * f0.y, w0 * f1.x, w0 * f1.y);

    for (int j = beg; j < end; j += 32) {
        int myidx = 0;
        float myw = 0.f;
        if (j + lane < end) {
            myidx = g_csr[j + lane];
            myw = g_dinv[myidx] * wd;
        }
        int cnt = min(32, end - j);
        int t = 0;
        for (; t + 1 < cnt; t += 2) {
            int s0    = __shfl_sync(0xffffffffu, myidx, t);
            float ww0 = __shfl_sync(0xffffffffu, myw, t);
            int s1    = __shfl_sync(0xffffffffu, myidx, t + 1);
            float ww1 = __shfl_sync(0xffffffffu, myw, t + 1);
            float2 a0, a1, b0, b1;
            loadrow(s0, a0, a1);
            loadrow(s1, b0, b1);
            acc.x = fmaf(ww0, a0.x, acc.x); acc.y = fmaf(ww0, a0.y, acc.y);
            acc.z = fmaf(ww0, a1.x, acc.z); acc.w = fmaf(ww0, a1.y, acc.w);
            acc.x = fmaf(ww1, b0.x, acc.x); acc.y = fmaf(ww1, b0.y, acc.y);
            acc.z = fmaf(ww1, b1.x, acc.z); acc.w = fmaf(ww1, b1.y, acc.w);
        }
        if (t < cnt) {
            int s0    = __shfl_sync(0xffffffffu, myidx, t);
            float ww0 = __shfl_sync(0xffffffffu, myw, t);
            float2 a0, a1;
            loadrow(s0, a0, a1);
            acc.x = fmaf(ww0, a0.x, acc.x); acc.y = fmaf(ww0, a0.y, acc.y);
            acc.z = fmaf(ww0, a1.x, acc.z); acc.w = fmaf(ww0, a1.y, acc.w);
        }
    }
    ((float4*)(g_acc + (size_t)d * D))[lane] = acc;
}

// ---------------- kernel 6: colstats1 + grid sync + BN2 affine + apply ------
__global__ void k_cf(float* __restrict__ out, int N,
                     const float* __restrict__ gam2,
                     const float* __restrict__ bet2, float invN, int nblk) {
    __shared__ __align__(16) float ss[8][D], sr[8][D];
    __shared__ float sa[D], sc_[D];
    int tid = threadIdx.x;
    int wid = tid >> 5, lane = tid & 31;

    // ---- phase 1: stats over g_acc ----
    float4 s = make_float4(0.f, 0.f, 0.f, 0.f);
    float4 q = make_float4(0.f, 0.f, 0.f, 0.f);
    for (int r = blockIdx.x * 8 + wid; r < N; r += nblk * 8) {
        float4 v = ((const float4*)(g_acc + (size_t)r * D))[lane];
        s.x += v.x; s.y += v.y; s.z += v.z; s.w += v.w;
        q.x += v.x * v.x; q.y += v.y * v.y; q.z += v.z * v.z; q.w += v.w * v.w;
    }
    ((float4*)ss[wid])[lane] = s;
    ((float4*)sr[wid])[lane] = q;
    __syncthreads();
    if (tid < D) {
        float a = 0.f, b = 0.f;
        #pragma unroll
        for (int wv = 0; wv < 8; wv++) { a += ss[wv][tid]; b += sr[wv][tid]; }
        atomicAdd(&g_sum2[tid], a);
        atomicAdd(&g_sq2[tid], b);
    }
    __threadfence();
    __syncthreads();
    // ---- grid-wide sync (all nblk blocks resident) ----
    if (tid == 0) {
        atomicAdd(&g_ctr[1], 1);
        while (atomicAdd(&g_ctr[1], 0) < nblk) __nanosleep(64);
    }
    __syncthreads();
    __threadfence();
    // ---- compute BN2 affine locally ----
    if (tid < D) {
        float mean = __ldcg(&g_sum2[tid]) * invN;
        float var  = __ldcg(&g_sq2[tid]) * invN - mean * mean;
        float scv = gam2[tid] * rsqrtf(var + BN_EPS);
        sa[tid] = scv;
        sc_[tid] = bet2[tid] - mean * scv;
    }
    __syncthreads();
    // ---- phase 2: apply BN2 + ReLU, write out (g_acc re-read hits L2) ----
    int c = lane * 4;
    float a0 = sa[c + 0], a1 = sa[c + 1], a2v = sa[c + 2], a3 = sa[c + 3];
    float c0 = sc_[c + 0], c1 = sc_[c + 1], c2v = sc_[c + 2], c3 = sc_[c + 3];
    for (int r = blockIdx.x * 8 + wid; r < N; r += nblk * 8) {
        float4 v = ((const float4*)(g_acc + (size_t)r * D))[lane];
        v.x = fmaxf(fmaf(v.x, a0, c0), 0.f);
        v.y = fmaxf(fmaf(v.y, a1, c1), 0.f);
        v.z = fmaxf(fmaf(v.z, a2v, c2v), 0.f);
        v.w = fmaxf(fmaf(v.w, a3, c3), 0.f);
        ((float4*)(out + (size_t)r * D))[lane] = v;
    }
}

// ---------------- launch ----------------
extern "C" void kernel_launch(void* const* d_in, const int* in_sizes, int n_in,
                              void* d_out, int out_size) {
    const float* x    = (const float*)d_in[0];
    const int*   ei   = (const int*)d_in[1];   // int64 in reference -> delivered int32
    const float* Wm   = (const float*)d_in[2];
    // d_in[3] = b_mlp  : cancels inside training-mode BatchNorm
    const float* gam1 = (const float*)d_in[4];
    const float* bet1 = (const float*)d_in[5];
    const float* Wc   = (const float*)d_in[6];
    // d_in[7] = b_conv : cancels inside training-mode BatchNorm
    const float* gam2 = (const float*)d_in[8];
    const float* bet2 = (const float*)d_in[9];
    float* out = (float*)d_out;

    const int N = in_sizes[0] / D;
    const int E = in_sizes[1] / 2;
    const int* srcp = ei;
    const int* dstp = ei + E;
    const float invN = 1.0f / (float)N;
    const int nchunks = (N + 511) / 512;
    const int EB = (E + 255) / 256;
    const int GB = (N + 127) / 128;

    k_pack<<<64, 256>>>(Wm, Wc, N);                       // + all state resets
    k_g0<<<GB + EB, 256>>>(x, dstp, E, N, GB);            // gemm0 + deg
    k_cs0s1<<<256 + nchunks, 256>>>(N, gam1, bet1, invN, nchunks);
    k_g1s3f<<<GB + nchunks, 256>>>(srcp, dstp, E, N, GB, nchunks);  // gemm1+scan3+fill
    k_gather<<<(N * 32 + 255) / 256, 256>>>(N);
    k_cf<<<256, 256>>>(out, N, gam2, bet2, invN, 256);    // colstats1+affine+final
}

// round 16
// speedup vs baseline: 1.0914x; 1.0914x over previous
#include <cuda_runtime.h>
#include <cuda_bf16.h>
#include <cuda_fp16.h>
#include <stdint.h>

#define D 128
#define MAXN 50048
#define MAXE 600064
#define BN_EPS 1e-5f
#define MAXCHUNKS 128

// ---------------- scratch (no allocation allowed) ----------------
__device__ float  g_h  [(size_t)MAXN * D];  // x@W_mlp (raw, pre-BN)
__device__ __half g_hch[(size_t)MAXN * D];  // relu(bn1(h)) @ W_conv, fp16 (gather-only)
__device__ float  g_acc[(size_t)MAXN * D];  // GCN aggregation result
__device__ int    g_degi[MAXN];
__device__ float  g_dinv[MAXN];
__device__ int    g_coff[MAXN + 1];
__device__ int    g_cursor[MAXN];
__device__ int    g_csr[MAXE];
__device__ int    g_part[MAXCHUNKS];
__device__ int    g_pbase[MAXCHUNKS];
__device__ float  g_sum1[D], g_sq1[D], g_sum2[D], g_sq2[D];
__device__ float  g_a1[D], g_c1[D];
__device__ int    g_ctr[4];                 // phase counters (reset in k_pack)
__device__ uint32_t g_Bph[2][64 * D];       // packed bf16 hi planes
__device__ uint32_t g_Bpl[2][64 * D];       // packed bf16 lo planes

// ---------------- bf16 split helpers ----------------
__device__ __forceinline__ void split_bf16(float v, float& hi, float& lo) {
    __nv_bfloat16 h = __float2bfloat16_rn(v);
    hi = __bfloat162float(h);
    lo = v - hi;
}
__device__ __forceinline__ uint32_t pack_bf16x2(float a, float b) {
    __nv_bfloat162 p = __floats2bfloat162_rn(a, b);
    return *reinterpret_cast<uint32_t*>(&p);
}
__device__ __forceinline__ void mma_bf16(float* c, const uint32_t* a,
                                         uint32_t b0, uint32_t b1) {
    asm volatile(
        "mma.sync.aligned.m16n8k16.row.col.f32.bf16.bf16.f32 "
        "{%0,%1,%2,%3}, {%4,%5,%6,%7}, {%8,%9}, {%0,%1,%2,%3};"
        : "+f"(c[0]), "+f"(c[1]), "+f"(c[2]), "+f"(c[3])
        : "r"(a[0]), "r"(a[1]), "r"(a[2]), "r"(a[3]), "r"(b0), "r"(b1));
}

// ---------------- pack weights + reset ALL cross-call state -----------------
__global__ void k_pack(const float* __restrict__ Wm, const float* __restrict__ Wc,
                       int N) {
    if (blockIdx.x == 0) {
        if (threadIdx.x < 4) g_ctr[threadIdx.x] = 0;
        if (threadIdx.x < D) {
            g_sum1[threadIdx.x] = 0.f; g_sq1[threadIdx.x] = 0.f;
            g_sum2[threadIdx.x] = 0.f; g_sq2[threadIdx.x] = 0.f;
        }
    }
    for (int i = blockIdx.x * 256 + threadIdx.x; i < N; i += gridDim.x * 256)
        g_degi[i] = 0;

    int idx = blockIdx.x * blockDim.x + threadIdx.x;   // 0..16383
    if (idx < 2 * 64 * D) {
        int m = idx >> 13;
        int rest = idx & 8191;         // k2*128 + col
        int k2 = rest >> 7, col = rest & 127;
        const float* W = (m == 0) ? Wm : Wc;
        float v0 = W[(2 * k2) * D + col];
        float v1 = W[(2 * k2 + 1) * D + col];
        float h0, l0, h1, l1;
        split_bf16(v0, h0, l0);
        split_bf16(v1, h1, l1);
        g_Bph[m][rest] = pack_bf16x2(h0, h1);
        g_Bpl[m][rest] = pack_bf16x2(l0, l1);
    }
}

// ---------------- bf16x3 MMA GEMM body ----------------
// MODE 0: A=x -> g_h (fp32). MODE 1: A=g_h + BN1 affine + ReLU -> g_hch (fp16).
#define APST 12
#define BPST 136
template <int MODE>
__device__ __forceinline__ void gemm_body(const float* __restrict__ Ain, int M, int blk) {
    __shared__ __align__(16) uint32_t Ahp[2][128 * APST], Alp[2][128 * APST];
    __shared__ __align__(16) uint32_t Bhp[2][8 * BPST],   Blp[2][8 * BPST];
    const float* A = (MODE == 0) ? Ain : g_h;

    const int tid  = threadIdx.x;
    const int w    = tid >> 5;
    const int lane = tid & 31;
    const int g    = lane >> 2;
    const int t    = lane & 3;
    const int row0 = blk * 128;

    const int r0_ = tid >> 2,         c40 = tid & 3;
    const int r1_ = (tid + 256) >> 2, c41 = (tid + 256) & 3;
    const int gr0 = row0 + r0_, gr1 = row0 + r1_;

    float acc[16][4];
    #pragma unroll
    for (int n = 0; n < 16; n++)
        #pragma unroll
        for (int i = 0; i < 4; i++) acc[n][i] = 0.f;

    auto loadA = [&](int kk, float4& v0, float4& v1) {
        v0 = make_float4(0.f, 0.f, 0.f, 0.f);
        v1 = make_float4(0.f, 0.f, 0.f, 0.f);
        if (gr0 < M) v0 = *(const float4*)(A + (size_t)gr0 * D + kk + c40 * 4);
        if (gr1 < M) v1 = *(const float4*)(A + (size_t)gr1 * D + kk + c41 * 4);
    };
    auto convertA = [&](int kk, int buf, float4 v0, float4 v1) {
        #pragma unroll
        for (int i = 0; i < 2; i++) {
            float4 v = i ? v1 : v0;
            int r = i ? r1_ : r0_;
            int c4 = i ? c41 : c40;
            if (MODE == 1) {
                int c = kk + c4 * 4;
                v.x = fmaxf(fmaf(v.x, g_a1[c + 0], g_c1[c + 0]), 0.f);
                v.y = fmaxf(fmaf(v.y, g_a1[c + 1], g_c1[c + 1]), 0.f);
                v.z = fmaxf(fmaf(v.z, g_a1[c + 2], g_c1[c + 2]), 0.f);
                v.w = fmaxf(fmaf(v.w, g_a1[c + 3], g_c1[c + 3]), 0.f);
            }
            float hx, lx, hy, ly, hz, lz, hw, lw;
            split_bf16(v.x, hx, lx); split_bf16(v.y, hy, ly);
            split_bf16(v.z, hz, lz); split_bf16(v.w, hw, lw);
            uint32_t* ph = &Ahp[buf][r * APST + c4 * 2];
            uint32_t* pl = &Alp[buf][r * APST + c4 * 2];
            ph[0] = pack_bf16x2(hx, hy); ph[1] = pack_bf16x2(hz, hw);
            pl[0] = pack_bf16x2(lx, ly); pl[1] = pack_bf16x2(lz, lw);
        }
    };
    auto issueB = [&](int c, int buf) {
        int k2l = tid >> 5, c4 = tid & 31;
        int srcw = (c * 8 + k2l) * D + c4 * 4;
        uint32_t dh = (uint32_t)__cvta_generic_to_shared(&Bhp[buf][k2l * BPST + c4 * 4]);
        uint32_t dl = (uint32_t)__cvta_generic_to_shared(&Blp[buf][k2l * BPST + c4 * 4]);
        asm volatile("cp.async.cg.shared.global [%0], [%1], 16;\n"
                     :: "r"(dh), "l"(&g_Bph[MODE][srcw]));
        asm volatile("cp.async.cg.shared.global [%0], [%1], 16;\n"
                     :: "r"(dl), "l"(&g_Bpl[MODE][srcw]));
        asm volatile("cp.async.commit_group;\n");
    };

    {
        float4 v0, v1;
        loadA(0, v0, v1);
        issueB(0, 0);
        convertA(0, 0, v0, v1);
        asm volatile("cp.async.wait_group 0;\n");
    }
    __syncthreads();

    for (int c = 0; c < 8; c++) {
        const int buf = c & 1, nb = buf ^ 1;
        const int kk = c * 16;
        float4 v0, v1;
        if (c < 7) {
            loadA(kk + 16, v0, v1);
            issueB(c + 1, nb);
        }

        uint32_t ah[4], al[4];
        {
            int ra = (w * 16 + g) * APST + t;
            int rb = (w * 16 + g + 8) * APST + t;
            ah[0] = Ahp[buf][ra];     ah[1] = Ahp[buf][rb];
            ah[2] = Ahp[buf][ra + 4]; ah[3] = Ahp[buf][rb + 4];
            al[0] = Alp[buf][ra];     al[1] = Alp[buf][rb];
            al[2] = Alp[buf][ra + 4]; al[3] = Alp[buf][rb + 4];
        }
        #pragma unroll
        for (int nt = 0; nt < 16; nt++) {
            int bi = t * BPST + nt * 8 + g;
            uint32_t bh0 = Bhp[buf][bi], bh1 = Bhp[buf][bi + 4 * BPST];
            uint32_t bl0 = Blp[buf][bi], bl1 = Blp[buf][bi + 4 * BPST];
            mma_bf16(acc[nt], ah, bh0, bh1);
            mma_bf16(acc[nt], ah, bl0, bl1);
            mma_bf16(acc[nt], al, bh0, bh1);
        }

        if (c < 7) {
            convertA(kk + 16, nb, v0, v1);
            asm volatile("cp.async.wait_group 0;\n");
            __syncthreads();
        }
    }

    int rA = row0 + w * 16 + g;
    int rB = rA + 8;
    #pragma unroll
    for (int nt = 0; nt < 16; nt++) {
        int col = nt * 8 + 2 * t;
        if (MODE == 0) {
            if (rA < M)
                *(float2*)(g_h + (size_t)rA * D + col) = make_float2(acc[nt][0], acc[nt][1]);
            if (rB < M)
                *(float2*)(g_h + (size_t)rB * D + col) = make_float2(acc[nt][2], acc[nt][3]);
        } else {
            if (rA < M)
                *(__half2*)(g_hch + (size_t)rA * D + col) =
                    __floats2half2_rn(acc[nt][0], acc[nt][1]);
            if (rB < M)
                *(__half2*)(g_hch + (size_t)rB * D + col) =
                    __floats2half2_rn(acc[nt][2], acc[nt][3]);
        }
    }
}

// ---------------- merged kernel 2: gemm0 + degree histogram -----------------
__global__ void __launch_bounds__(256, 2) k_g0(const float* __restrict__ x,
                                               const int* __restrict__ dst,
                                               int E, int N, int GB) {
    if ((int)blockIdx.x < GB) {
        gemm_body<0>(x, N, blockIdx.x);
    } else {
        int e = (blockIdx.x - GB) * 256 + threadIdx.x;
        if (e < E) {
            int d = dst[e];
            if ((unsigned)d < (unsigned)N) atomicAdd(&g_degi[d], 1);
        }
    }
}

// ---------------- merged kernel 3: colstats0(+BN1 affine) + scan1/2 ---------
__global__ void k_cs0s1(int N, const float* __restrict__ gam1,
                        const float* __restrict__ bet1, float invN, int nchunks) {
    if (blockIdx.x < 256) {
        // ---- colstats0 over g_h; last block computes BN1 affine ----
        __shared__ __align__(16) float ss[8][D], sr[8][D];
        __shared__ int lastblk;
        int tid = threadIdx.x;
        int wid = tid >> 5, lane = tid & 31;
        float4 s = make_float4(0.f, 0.f, 0.f, 0.f);
        float4 q = make_float4(0.f, 0.f, 0.f, 0.f);
        for (int r = blockIdx.x * 8 + wid; r < N; r += 256 * 8) {
            float4 v = ((const float4*)(g_h + (size_t)r * D))[lane];
            s.x += v.x; s.y += v.y; s.z += v.z; s.w += v.w;
            q.x += v.x * v.x; q.y += v.y * v.y; q.z += v.z * v.z; q.w += v.w * v.w;
        }
        ((float4*)ss[wid])[lane] = s;
        ((float4*)sr[wid])[lane] = q;
        __syncthreads();
        if (tid < D) {
            float a = 0.f, b = 0.f;
            #pragma unroll
            for (int wv = 0; wv < 8; wv++) { a += ss[wv][tid]; b += sr[wv][tid]; }
            atomicAdd(&g_sum1[tid], a);
            atomicAdd(&g_sq1[tid], b);
        }
        __threadfence();
        __syncthreads();
        if (tid == 0) {
            int ret = atomicAdd(&g_ctr[0], 1);
            lastblk = (ret == 255);
        }
        __syncthreads();
        if (lastblk && tid < D) {
            float mean = __ldcg(&g_sum1[tid]) * invN;
            float var  = __ldcg(&g_sq1[tid]) * invN - mean * mean;
            float sc = gam1[tid] * rsqrtf(var + BN_EPS);
            g_a1[tid] = sc;
            g_c1[tid] = bet1[tid] - mean * sc;
        }
        return;
    }
    // ---- scan1: per-chunk degree sums; phase 2 in last block ----
    __shared__ int red[256];
    __shared__ int lastblk1;
    int chunk = blockIdx.x - 256;
    int tid = threadIdx.x;
    int i0 = chunk * 512 + 2 * tid;
    int d0 = (i0 < N) ? g_degi[i0] : 0;
    int d1 = (i0 + 1 < N) ? g_degi[i0 + 1] : 0;
    red[tid] = d0 + d1;
    __syncthreads();
    #pragma unroll
    for (int off = 128; off > 0; off >>= 1) {
        if (tid < off) red[tid] += red[tid + off];
        __syncthreads();
    }
    if (tid == 0) g_part[chunk] = red[0];
    __threadfence();
    __syncthreads();
    if (tid == 0) {
        int ret = atomicAdd(&g_ctr[2], 1);
        lastblk1 = (ret == nchunks - 1);
    }
    __syncthreads();
    if (!lastblk1) return;

    __shared__ int s[MAXCHUNKS];
    if (tid < MAXCHUNKS)
        s[tid] = (tid < nchunks) ? __ldcg(&g_part[tid]) : 0;
    __syncthreads();
    #pragma unroll
    for (int off = 1; off < MAXCHUNKS; off <<= 1) {
        int v = 0, u = 0;
        if (tid < MAXCHUNKS) { v = s[tid]; u = (tid >= off) ? s[tid - off] : 0; }
        __syncthreads();
        if (tid < MAXCHUNKS) s[tid] = v + u;
        __syncthreads();
    }
    if (tid < nchunks) g_pbase[tid] = (tid > 0) ? s[tid - 1] : 0;
}

// ---------------- merged kernel 4: gemm1 + scan3 ----------------------------
__global__ void __launch_bounds__(256, 2) k_g1s3(int N, int GB) {
    if ((int)blockIdx.x < GB) {
        gemm_body<1>(nullptr, N, blockIdx.x);
        return;
    }
    // ---- scan3: intra-chunk exclusive scan + dinv ----
    __shared__ int sp[256];
    int chunk = blockIdx.x - GB;
    int tid = threadIdx.x;
    int i0 = chunk * 512 + 2 * tid;
    int d0 = (i0 < N) ? g_degi[i0] : 0;
    int d1 = (i0 + 1 < N) ? g_degi[i0 + 1] : 0;
    int ps = d0 + d1;
    sp[tid] = ps;
    __syncthreads();
    #pragma unroll
    for (int off = 1; off < 256; off <<= 1) {
        int v = sp[tid];
        int u = (tid >= off) ? sp[tid - off] : 0;
        __syncthreads();
        sp[tid] = v + u;
        __syncthreads();
    }
    int base = g_pbase[chunk];
    int excl = base + sp[tid] - ps;
    if (i0 < N) {
        g_coff[i0] = excl;
        g_cursor[i0] = excl;
        g_dinv[i0] = rsqrtf((float)d0 + 1.0f);
        if (i0 == N - 1) g_coff[N] = excl + d0;
    }
    if (i0 + 1 < N) {
        g_coff[i0 + 1] = excl + d0;
        g_cursor[i0 + 1] = excl + d0;
        g_dinv[i0 + 1] = rsqrtf((float)d1 + 1.0f);
        if (i0 + 1 == N - 1) g_coff[N] = excl + d0 + d1;
    }
}

// ---------------- CSR fill (wide grid) ----------------
__global__ void k_fill(const int* __restrict__ src,
                       const int* __restrict__ dst, int E, int N) {
    int e = blockIdx.x * blockDim.x + threadIdx.x;
    if (e < E) {
        int d = dst[e], s = src[e];
        if ((unsigned)d < (unsigned)N && (unsigned)s < (unsigned)N) {
            int pos = atomicAdd(&g_cursor[d], 1);
            g_csr[pos] = s;
        }
    }
}

// ---------------- gather aggregation (fp16 rows): warp per destination ------
__global__ void k_gather(int N) {
    int w = (blockIdx.x * blockDim.x + threadIdx.x) >> 5;
    int lane = threadIdx.x & 31;
    if (w >= N) return;
    int d = w;
    int beg = g_coff[d], end = g_coff[d + 1];
    float wd = g_dinv[d];

    auto loadrow = [&](int row, float2& f0, float2& f1) {
        uint2 raw = *(const uint2*)(g_hch + (size_t)row * D + lane * 4);
        f0 = __half22float2(*(__half2*)&raw.x);
        f1 = __half22float2(*(__half2*)&raw.y);
    };

    float2 f0, f1;
    loadrow(d, f0, f1);
    float w0 = wd * wd;
    float4 acc = make_float4(w0 * f0.x, w0 * f0.y, w0 * f1.x, w0 * f1.y);

    for (int j = beg; j < end; j += 32) {
        int myidx = 0;
        float myw = 0.f;
        if (j + lane < end) {
            myidx = g_csr[j + lane];
            myw = g_dinv[myidx] * wd;
        }
        int cnt = min(32, end - j);
        int t = 0;
        for (; t + 1 < cnt; t += 2) {
            int s0    = __shfl_sync(0xffffffffu, myidx, t);
            float ww0 = __shfl_sync(0xffffffffu, myw, t);
            int s1    = __shfl_sync(0xffffffffu, myidx, t + 1);
            float ww1 = __shfl_sync(0xffffffffu, myw, t + 1);
            float2 a0, a1, b0, b1;
            loadrow(s0, a0, a1);
            loadrow(s1, b0, b1);
            acc.x = fmaf(ww0, a0.x, acc.x); acc.y = fmaf(ww0, a0.y, acc.y);
            acc.z = fmaf(ww0, a1.x, acc.z); acc.w = fmaf(ww0, a1.y, acc.w);
            acc.x = fmaf(ww1, b0.x, acc.x); acc.y = fmaf(ww1, b0.y, acc.y);
            acc.z = fmaf(ww1, b1.x, acc.z); acc.w = fmaf(ww1, b1.y, acc.w);
        }
        if (t < cnt) {
            int s0    = __shfl_sync(0xffffffffu, myidx, t);
            float ww0 = __shfl_sync(0xffffffffu, myw, t);
            float2 a0, a1;
            loadrow(s0, a0, a1);
            acc.x = fmaf(ww0, a0.x, acc.x); acc.y = fmaf(ww0, a0.y, acc.y);
            acc.z = fmaf(ww0, a1.x, acc.z); acc.w = fmaf(ww0, a1.y, acc.w);
        }
    }
    ((float4*)(g_acc + (size_t)d * D))[lane] = acc;
}

// ---------------- kernel 7: colstats1 + grid sync + BN2 affine + apply ------
__global__ void k_cf(float* __restrict__ out, int N,
                     const float* __restrict__ gam2,
                     const float* __restrict__ bet2, float invN, int nblk) {
    __shared__ __align__(16) float ss[8][D], sr[8][D];
    __shared__ float sa[D], sc_[D];
    int tid = threadIdx.x;
    int wid = tid >> 5, lane = tid & 31;

    // ---- phase 1: stats over g_acc ----
    float4 s = make_float4(0.f, 0.f, 0.f, 0.f);
    float4 q = make_float4(0.f, 0.f, 0.f, 0.f);
    for (int r = blockIdx.x * 8 + wid; r < N; r += nblk * 8) {
        float4 v = ((const float4*)(g_acc + (size_t)r * D))[lane];
        s.x += v.x; s.y += v.y; s.z += v.z; s.w += v.w;
        q.x += v.x * v.x; q.y += v.y * v.y; q.z += v.z * v.z; q.w += v.w * v.w;
    }
    ((float4*)ss[wid])[lane] = s;
    ((float4*)sr[wid])[lane] = q;
    __syncthreads();
    if (tid < D) {
        float a = 0.f, b = 0.f;
        #pragma unroll
        for (int wv = 0; wv < 8; wv++) { a += ss[wv][tid]; b += sr[wv][tid]; }
        atomicAdd(&g_sum2[tid], a);
        atomicAdd(&g_sq2[tid], b);
    }
    __threadfence();
    __syncthreads();
    // ---- grid-wide sync (all nblk blocks resident) ----
    if (tid == 0) {
        atomicAdd(&g_ctr[1], 1);
        while (atomicAdd(&g_ctr[1], 0) < nblk) __nanosleep(64);
    }
    __syncthreads();
    __threadfence();
    // ---- compute BN2 affine locally ----
    if (tid < D) {
        float mean = __ldcg(&g_sum2[tid]) * invN;
        float var  = __ldcg(&g_sq2[tid]) * invN - mean * mean;
        float scv = gam2[tid] * rsqrtf(var + BN_EPS);
        sa[tid] = scv;
        sc_[tid] = bet2[tid] - mean * scv;
    }
    __syncthreads();
    // ---- phase 2: apply BN2 + ReLU, write out (g_acc re-read hits L2) ----
    int c = lane * 4;
    float a0 = sa[c + 0], a1 = sa[c + 1], a2v = sa[c + 2], a3 = sa[c + 3];
    float c0 = sc_[c + 0], c1 = sc_[c + 1], c2v = sc_[c + 2], c3 = sc_[c + 3];
    for (int r = blockIdx.x * 8 + wid; r < N; r += nblk * 8) {
        float4 v = ((const float4*)(g_acc + (size_t)r * D))[lane];
        v.x = fmaxf(fmaf(v.x, a0, c0), 0.f);
        v.y = fmaxf(fmaf(v.y, a1, c1), 0.f);
        v.z = fmaxf(fmaf(v.z, a2v, c2v), 0.f);
        v.w = fmaxf(fmaf(v.w, a3, c3), 0.f);
        ((float4*)(out + (size_t)r * D))[lane] = v;
    }
}

// ---------------- launch ----------------
extern "C" void kernel_launch(void* const* d_in, const int* in_sizes, int n_in,
                              void* d_out, int out_size) {
    const float* x    = (const float*)d_in[0];
    const int*   ei   = (const int*)d_in[1];   // int64 in reference -> delivered int32
    const float* Wm   = (const float*)d_in[2];
    // d_in[3] = b_mlp  : cancels inside training-mode BatchNorm
    const float* gam1 = (const float*)d_in[4];
    const float* bet1 = (const float*)d_in[5];
    const float* Wc   = (const float*)d_in[6];
    // d_in[7] = b_conv : cancels inside training-mode BatchNorm
    const float* gam2 = (const float*)d_in[8];
    const float* bet2 = (const float*)d_in[9];
    float* out = (float*)d_out;

    const int N = in_sizes[0] / D;
    const int E = in_sizes[1] / 2;
    const int* srcp = ei;
    const int* dstp = ei + E;
    const float invN = 1.0f / (float)N;
    const int nchunks = (N + 511) / 512;
    const int EB = (E + 255) / 256;
    const int GB = (N + 127) / 128;

    k_pack<<<64, 256>>>(Wm, Wc, N);                       // + all state resets
    k_g0<<<GB + EB, 256>>>(x, dstp, E, N, GB);            // gemm0 + deg
    k_cs0s1<<<256 + nchunks, 256>>>(N, gam1, bet1, invN, nchunks);
    k_g1s3<<<GB + nchunks, 256>>>(N, GB);                 // gemm1 + scan3
    k_fill<<<EB, 256>>>(srcp, dstp, E, N);
    k_gather<<<(N * 32 + 255) / 256, 256>>>(N);
    k_cf<<<256, 256>>>(out, N, gam2, bet2, invN, 256);    // colstats1+affine+final
}

// round 17
// speedup vs baseline: 1.1339x; 1.0389x over previous
#include <cuda_runtime.h>
#include <cuda_bf16.h>
#include <cuda_fp16.h>
#include <stdint.h>

#define D 128
#define MAXN 50048
#define MAXE 600064
#define BN_EPS 1e-5f
#define MAXCHUNKS 128

// ---------------- scratch (no allocation allowed) ----------------
__device__ float  g_h  [(size_t)MAXN * D];  // x@W_mlp (raw, pre-BN)
__device__ __half g_hch[(size_t)MAXN * D];  // relu(bn1(h)) @ W_conv, fp16 (gather-only)
__device__ float  g_acc[(size_t)MAXN * D];  // GCN aggregation result
__device__ int    g_degi[MAXN];
__device__ float  g_dinv[MAXN];
__device__ int    g_coff[MAXN + 1];
__device__ int    g_cursor[MAXN];
__device__ int    g_csr[MAXE];
__device__ int    g_part[MAXCHUNKS];
__device__ float  g_sum1[D], g_sq1[D], g_sum2[D], g_sq2[D];
__device__ float  g_a1[D], g_c1[D];
__device__ int    g_ctr[4];                 // phase counters (reset in k_pack)
__device__ uint32_t g_Bph[2][64 * D];       // packed bf16 hi planes
__device__ uint32_t g_Bpl[2][64 * D];       // packed bf16 lo planes

// ---------------- bf16 split helpers ----------------
__device__ __forceinline__ void split_bf16(float v, float& hi, float& lo) {
    __nv_bfloat16 h = __float2bfloat16_rn(v);
    hi = __bfloat162float(h);
    lo = v - hi;
}
__device__ __forceinline__ uint32_t pack_bf16x2(float a, float b) {
    __nv_bfloat162 p = __floats2bfloat162_rn(a, b);
    return *reinterpret_cast<uint32_t*>(&p);
}
__device__ __forceinline__ void mma_bf16(float* c, const uint32_t* a,
                                         uint32_t b0, uint32_t b1) {
    asm volatile(
        "mma.sync.aligned.m16n8k16.row.col.f32.bf16.bf16.f32 "
        "{%0,%1,%2,%3}, {%4,%5,%6,%7}, {%8,%9}, {%0,%1,%2,%3};"
        : "+f"(c[0]), "+f"(c[1]), "+f"(c[2]), "+f"(c[3])
        : "r"(a[0]), "r"(a[1]), "r"(a[2]), "r"(a[3]), "r"(b0), "r"(b1));
}

// ---------------- pack weights + reset ALL cross-call state -----------------
__global__ void k_pack(const float* __restrict__ Wm, const float* __restrict__ Wc,
                       int N) {
    if (blockIdx.x == 0) {
        if (threadIdx.x < 4) g_ctr[threadIdx.x] = 0;
        if (threadIdx.x < D) {
            g_sum1[threadIdx.x] = 0.f; g_sq1[threadIdx.x] = 0.f;
            g_sum2[threadIdx.x] = 0.f; g_sq2[threadIdx.x] = 0.f;
        }
    }
    for (int i = blockIdx.x * 256 + threadIdx.x; i < N; i += gridDim.x * 256)
        g_degi[i] = 0;

    int idx = blockIdx.x * blockDim.x + threadIdx.x;   // 0..16383
    if (idx < 2 * 64 * D) {
        int m = idx >> 13;
        int rest = idx & 8191;         // k2*128 + col
        int k2 = rest >> 7, col = rest & 127;
        const float* W = (m == 0) ? Wm : Wc;
        float v0 = W[(2 * k2) * D + col];
        float v1 = W[(2 * k2 + 1) * D + col];
        float h0, l0, h1, l1;
        split_bf16(v0, h0, l0);
        split_bf16(v1, h1, l1);
        g_Bph[m][rest] = pack_bf16x2(h0, h1);
        g_Bpl[m][rest] = pack_bf16x2(l0, l1);
    }
}

// ---------------- bf16x3 MMA GEMM body ----------------
// MODE 0: A=x -> g_h (fp32). MODE 1: A=g_h + BN1 affine + ReLU -> g_hch (fp16).
#define APST 12
#define BPST 136
template <int MODE>
__device__ __forceinline__ void gemm_body(const float* __restrict__ Ain, int M, int blk) {
    __shared__ __align__(16) uint32_t Ahp[2][128 * APST], Alp[2][128 * APST];
    __shared__ __align__(16) uint32_t Bhp[2][8 * BPST],   Blp[2][8 * BPST];
    const float* A = (MODE == 0) ? Ain : g_h;

    const int tid  = threadIdx.x;
    const int w    = tid >> 5;
    const int lane = tid & 31;
    const int g    = lane >> 2;
    const int t    = lane & 3;
    const int row0 = blk * 128;

    const int r0_ = tid >> 2,         c40 = tid & 3;
    const int r1_ = (tid + 256) >> 2, c41 = (tid + 256) & 3;
    const int gr0 = row0 + r0_, gr1 = row0 + r1_;

    float acc[16][4];
    #pragma unroll
    for (int n = 0; n < 16; n++)
        #pragma unroll
        for (int i = 0; i < 4; i++) acc[n][i] = 0.f;

    auto loadA = [&](int kk, float4& v0, float4& v1) {
        v0 = make_float4(0.f, 0.f, 0.f, 0.f);
        v1 = make_float4(0.f, 0.f, 0.f, 0.f);
        if (gr0 < M) v0 = *(const float4*)(A + (size_t)gr0 * D + kk + c40 * 4);
        if (gr1 < M) v1 = *(const float4*)(A + (size_t)gr1 * D + kk + c41 * 4);
    };
    auto convertA = [&](int kk, int buf, float4 v0, float4 v1) {
        #pragma unroll
        for (int i = 0; i < 2; i++) {
            float4 v = i ? v1 : v0;
            int r = i ? r1_ : r0_;
            int c4 = i ? c41 : c40;
            if (MODE == 1) {
                int c = kk + c4 * 4;
                v.x = fmaxf(fmaf(v.x, g_a1[c + 0], g_c1[c + 0]), 0.f);
                v.y = fmaxf(fmaf(v.y, g_a1[c + 1], g_c1[c + 1]), 0.f);
                v.z = fmaxf(fmaf(v.z, g_a1[c + 2], g_c1[c + 2]), 0.f);
                v.w = fmaxf(fmaf(v.w, g_a1[c + 3], g_c1[c + 3]), 0.f);
            }
            float hx, lx, hy, ly, hz, lz, hw, lw;
            split_bf16(v.x, hx, lx); split_bf16(v.y, hy, ly);
            split_bf16(v.z, hz, lz); split_bf16(v.w, hw, lw);
            uint32_t* ph = &Ahp[buf][r * APST + c4 * 2];
            uint32_t* pl = &Alp[buf][r * APST + c4 * 2];
            ph[0] = pack_bf16x2(hx, hy); ph[1] = pack_bf16x2(hz, hw);
            pl[0] = pack_bf16x2(lx, ly); pl[1] = pack_bf16x2(lz, lw);
        }
    };
    auto issueB = [&](int c, int buf) {
        int k2l = tid >> 5, c4 = tid & 31;
        int srcw = (c * 8 + k2l) * D + c4 * 4;
        uint32_t dh = (uint32_t)__cvta_generic_to_shared(&Bhp[buf][k2l * BPST + c4 * 4]);
        uint32_t dl = (uint32_t)__cvta_generic_to_shared(&Blp[buf][k2l * BPST + c4 * 4]);
        asm volatile("cp.async.cg.shared.global [%0], [%1], 16;\n"
                     :: "r"(dh), "l"(&g_Bph[MODE][srcw]));
        asm volatile("cp.async.cg.shared.global [%0], [%1], 16;\n"
                     :: "r"(dl), "l"(&g_Bpl[MODE][srcw]));
        asm volatile("cp.async.commit_group;\n");
    };

    {
        float4 v0, v1;
        loadA(0, v0, v1);
        issueB(0, 0);
        convertA(0, 0, v0, v1);
        asm volatile("cp.async.wait_group 0;\n");
    }
    __syncthreads();

    for (int c = 0; c < 8; c++) {
        const int buf = c & 1, nb = buf ^ 1;
        const int kk = c * 16;
        float4 v0, v1;
        if (c < 7) {
            loadA(kk + 16, v0, v1);
            issueB(c + 1, nb);
        }

        uint32_t ah[4], al[4];
        {
            int ra = (w * 16 + g) * APST + t;
            int rb = (w * 16 + g + 8) * APST + t;
            ah[0] = Ahp[buf][ra];     ah[1] = Ahp[buf][rb];
            ah[2] = Ahp[buf][ra + 4]; ah[3] = Ahp[buf][rb + 4];
            al[0] = Alp[buf][ra];     al[1] = Alp[buf][rb];
            al[2] = Alp[buf][ra + 4]; al[3] = Alp[buf][rb + 4];
        }
        #pragma unroll
        for (int nt = 0; nt < 16; nt++) {
            int bi = t * BPST + nt * 8 + g;
            uint32_t bh0 = Bhp[buf][bi], bh1 = Bhp[buf][bi + 4 * BPST];
            uint32_t bl0 = Blp[buf][bi], bl1 = Blp[buf][bi + 4 * BPST];
            mma_bf16(acc[nt], ah, bh0, bh1);
            mma_bf16(acc[nt], ah, bl0, bl1);
            mma_bf16(acc[nt], al, bh0, bh1);
        }

        if (c < 7) {
            convertA(kk + 16, nb, v0, v1);
            asm volatile("cp.async.wait_group 0;\n");
            __syncthreads();
        }
    }

    int rA = row0 + w * 16 + g;
    int rB = rA + 8;
    #pragma unroll
    for (int nt = 0; nt < 16; nt++) {
        int col = nt * 8 + 2 * t;
        if (MODE == 0) {
            if (rA < M)
                *(float2*)(g_h + (size_t)rA * D + col) = make_float2(acc[nt][0], acc[nt][1]);
            if (rB < M)
                *(float2*)(g_h + (size_t)rB * D + col) = make_float2(acc[nt][2], acc[nt][3]);
        } else {
            if (rA < M)
                *(__half2*)(g_hch + (size_t)rA * D + col) =
                    __floats2half2_rn(acc[nt][0], acc[nt][1]);
            if (rB < M)
                *(__half2*)(g_hch + (size_t)rB * D + col) =
                    __floats2half2_rn(acc[nt][2], acc[nt][3]);
        }
    }
}

// ---------------- merged kernel 2: gemm0 + degree histogram -----------------
__global__ void __launch_bounds__(256, 2) k_g0(const float* __restrict__ x,
                                               const int* __restrict__ dst,
                                               int E, int N, int GB) {
    if ((int)blockIdx.x < GB) {
        gemm_body<0>(x, N, blockIdx.x);
    } else {
        int e = (blockIdx.x - GB) * 256 + threadIdx.x;
        if (e < E) {
            int d = dst[e];
            if ((unsigned)d < (unsigned)N) atomicAdd(&g_degi[d], 1);
        }
    }
}

// ---------------- merged kernel 3: colstats0(+BN1 affine) + FULL scan -------
// Scan blocks: chunk sums -> spin-sync(98) -> local base prefix -> intra-chunk
// exclusive scan -> coff/cursor/dinv. All blocks co-resident; no serial tail.
__global__ void k_cs0s1(int N, const float* __restrict__ gam1,
                        const float* __restrict__ bet1, float invN, int nchunks) {
    if (blockIdx.x < 256) {
        // ---- colstats0 over g_h; last block computes BN1 affine ----
        __shared__ __align__(16) float ss[8][D], sr[8][D];
        __shared__ int lastblk;
        int tid = threadIdx.x;
        int wid = tid >> 5, lane = tid & 31;
        float4 s = make_float4(0.f, 0.f, 0.f, 0.f);
        float4 q = make_float4(0.f, 0.f, 0.f, 0.f);
        for (int r = blockIdx.x * 8 + wid; r < N; r += 256 * 8) {
            float4 v = ((const float4*)(g_h + (size_t)r * D))[lane];
            s.x += v.x; s.y += v.y; s.z += v.z; s.w += v.w;
            q.x += v.x * v.x; q.y += v.y * v.y; q.z += v.z * v.z; q.w += v.w * v.w;
        }
        ((float4*)ss[wid])[lane] = s;
        ((float4*)sr[wid])[lane] = q;
        __syncthreads();
        if (tid < D) {
            float a = 0.f, b = 0.f;
            #pragma unroll
            for (int wv = 0; wv < 8; wv++) { a += ss[wv][tid]; b += sr[wv][tid]; }
            atomicAdd(&g_sum1[tid], a);
            atomicAdd(&g_sq1[tid], b);
        }
        __threadfence();
        __syncthreads();
        if (tid == 0) {
            int ret = atomicAdd(&g_ctr[0], 1);
            lastblk = (ret == 255);
        }
        __syncthreads();
        if (lastblk && tid < D) {
            float mean = __ldcg(&g_sum1[tid]) * invN;
            float var  = __ldcg(&g_sq1[tid]) * invN - mean * mean;
            float sc = gam1[tid] * rsqrtf(var + BN_EPS);
            g_a1[tid] = sc;
            g_c1[tid] = bet1[tid] - mean * sc;
        }
        return;
    }
    // ---- full scan in one kernel (chunk = blockIdx.x - 256) ----
    __shared__ int sp[256];
    __shared__ int sbase[256];
    int chunk = blockIdx.x - 256;
    int tid = threadIdx.x;
    int i0 = chunk * 512 + 2 * tid;
    int d0 = (i0 < N) ? g_degi[i0] : 0;
    int d1 = (i0 + 1 < N) ? g_degi[i0 + 1] : 0;
    int ps = d0 + d1;
    // chunk sum via reduction
    sp[tid] = ps;
    __syncthreads();
    #pragma unroll
    for (int off = 128; off > 0; off >>= 1) {
        if (tid < off) sp[tid] += sp[tid + off];
        __syncthreads();
    }
    if (tid == 0) g_part[chunk] = sp[0];
    __threadfence();
    __syncthreads();
    // spin-sync among all scan blocks (all resident)
    if (tid == 0) {
        atomicAdd(&g_ctr[2], 1);
        while (atomicAdd(&g_ctr[2], 0) < nchunks) __nanosleep(64);
    }
    __syncthreads();
    __threadfence();
    // local base = sum of parts before this chunk
    sbase[tid] = (tid < chunk) ? __ldcg(&g_part[tid]) : 0;
    __syncthreads();
    #pragma unroll
    for (int off = 128; off > 0; off >>= 1) {
        if (tid < off) sbase[tid] += sbase[tid + off];
        __syncthreads();
    }
    int base = sbase[0];
    __syncthreads();
    // intra-chunk inclusive pair-scan
    sp[tid] = ps;
    __syncthreads();
    #pragma unroll
    for (int off = 1; off < 256; off <<= 1) {
        int v = sp[tid];
        int u = (tid >= off) ? sp[tid - off] : 0;
        __syncthreads();
        sp[tid] = v + u;
        __syncthreads();
    }
    int excl = base + sp[tid] - ps;
    if (i0 < N) {
        g_coff[i0] = excl;
        g_cursor[i0] = excl;
        g_dinv[i0] = rsqrtf((float)d0 + 1.0f);
        if (i0 == N - 1) g_coff[N] = excl + d0;
    }
    if (i0 + 1 < N) {
        g_coff[i0 + 1] = excl + d0;
        g_cursor[i0 + 1] = excl + d0;
        g_dinv[i0 + 1] = rsqrtf((float)d1 + 1.0f);
        if (i0 + 1 == N - 1) g_coff[N] = excl + d0 + d1;
    }
}

// ---------------- merged kernel 4: gemm1 + CSR fill (independent!) ----------
__global__ void __launch_bounds__(256, 2) k_g1f(const int* __restrict__ src,
                                                const int* __restrict__ dst,
                                                int E, int N, int GB) {
    if ((int)blockIdx.x < GB) {
        gemm_body<1>(nullptr, N, blockIdx.x);
        return;
    }
    int e = (blockIdx.x - GB) * 256 + threadIdx.x;
    if (e < E) {
        int d = dst[e], s = src[e];
        if ((unsigned)d < (unsigned)N && (unsigned)s < (unsigned)N) {
            int pos = atomicAdd(&g_cursor[d], 1);
            g_csr[pos] = s;
        }
    }
}

// ---------------- gather aggregation (fp16 rows): warp per destination ------
__global__ void k_gather(int N) {
    int w = (blockIdx.x * blockDim.x + threadIdx.x) >> 5;
    int lane = threadIdx.x & 31;
    if (w >= N) return;
    int d = w;
    int beg = g_coff[d], end = g_coff[d + 1];
    float wd = g_dinv[d];

    auto loadrow = [&](int row, float2& f0, float2& f1) {
        uint2 raw = *(const uint2*)(g_hch + (size_t)row * D + lane * 4);
        f0 = __half22float2(*(__half2*)&raw.x);
        f1 = __half22float2(*(__half2*)&raw.y);
    };

    float2 f0, f1;
    loadrow(d, f0, f1);
    float w0 = wd * wd;
    float4 acc = make_float4(w0 * f0.x, w0 * f0.y, w0 * f1.x, w0 * f1.y);

    for (int j = beg; j < end; j += 32) {
        int myidx = 0;
        float myw = 0.f;
        if (j + lane < end) {
            myidx = g_csr[j + lane];
            myw = g_dinv[myidx] * wd;
        }
        int cnt = min(32, end - j);
        int t = 0;
        for (; t + 1 < cnt; t += 2) {
            int s0    = __shfl_sync(0xffffffffu, myidx, t);
            float ww0 = __shfl_sync(0xffffffffu, myw, t);
            int s1    = __shfl_sync(0xffffffffu, myidx, t + 1);
            float ww1 = __shfl_sync(0xffffffffu, myw, t + 1);
            float2 a0, a1, b0, b1;
            loadrow(s0, a0, a1);
            loadrow(s1, b0, b1);
            acc.x = fmaf(ww0, a0.x, acc.x); acc.y = fmaf(ww0, a0.y, acc.y);
            acc.z = fmaf(ww0, a1.x, acc.z); acc.w = fmaf(ww0, a1.y, acc.w);
            acc.x = fmaf(ww1, b0.x, acc.x); acc.y = fmaf(ww1, b0.y, acc.y);
            acc.z = fmaf(ww1, b1.x, acc.z); acc.w = fmaf(ww1, b1.y, acc.w);
        }
        if (t < cnt) {
            int s0    = __shfl_sync(0xffffffffu, myidx, t);
            float ww0 = __shfl_sync(0xffffffffu, myw, t);
            float2 a0, a1;
            loadrow(s0, a0, a1);
            acc.x = fmaf(ww0, a0.x, acc.x); acc.y = fmaf(ww0, a0.y, acc.y);
            acc.z = fmaf(ww0, a1.x, acc.z); acc.w = fmaf(ww0, a1.y, acc.w);
        }
    }
    ((float4*)(g_acc + (size_t)d * D))[lane] = acc;
}

// ---------------- kernel 6: colstats1 + grid sync + BN2 affine + apply ------
__global__ void k_cf(float* __restrict__ out, int N,
                     const float* __restrict__ gam2,
                     const float* __restrict__ bet2, float invN, int nblk) {
    __shared__ __align__(16) float ss[8][D], sr[8][D];
    __shared__ float sa[D], sc_[D];
    int tid = threadIdx.x;
    int wid = tid >> 5, lane = tid & 31;

    float4 s = make_float4(0.f, 0.f, 0.f, 0.f);
    float4 q = make_float4(0.f, 0.f, 0.f, 0.f);
    for (int r = blockIdx.x * 8 + wid; r < N; r += nblk * 8) {
        float4 v = ((const float4*)(g_acc + (size_t)r * D))[lane];
        s.x += v.x; s.y += v.y; s.z += v.z; s.w += v.w;
        q.x += v.x * v.x; q.y += v.y * v.y; q.z += v.z * v.z; q.w += v.w * v.w;
    }
    ((float4*)ss[wid])[lane] = s;
    ((float4*)sr[wid])[lane] = q;
    __syncthreads();
    if (tid < D) {
        float a = 0.f, b = 0.f;
        #pragma unroll
        for (int wv = 0; wv < 8; wv++) { a += ss[wv][tid]; b += sr[wv][tid]; }
        atomicAdd(&g_sum2[tid], a);
        atomicAdd(&g_sq2[tid], b);
    }
    __threadfence();
    __syncthreads();
    if (tid == 0) {
        atomicAdd(&g_ctr[1], 1);
        while (atomicAdd(&g_ctr[1], 0) < nblk) __nanosleep(64);
    }
    __syncthreads();
    __threadfence();
    if (tid < D) {
        float mean = __ldcg(&g_sum2[tid]) * invN;
        float var  = __ldcg(&g_sq2[tid]) * invN - mean * mean;
        float scv = gam2[tid] * rsqrtf(var + BN_EPS);
        sa[tid] = scv;
        sc_[tid] = bet2[tid] - mean * scv;
    }
    __syncthreads();
    int c = lane * 4;
    float a0 = sa[c + 0], a1 = sa[c + 1], a2v = sa[c + 2], a3 = sa[c + 3];
    float c0 = sc_[c + 0], c1 = sc_[c + 1], c2v = sc_[c + 2], c3 = sc_[c + 3];
    for (int r = blockIdx.x * 8 + wid; r < N; r += nblk * 8) {
        float4 v = ((const float4*)(g_acc + (size_t)r * D))[lane];
        v.x = fmaxf(fmaf(v.x, a0, c0), 0.f);
        v.y = fmaxf(fmaf(v.y, a1, c1), 0.f);
        v.z = fmaxf(fmaf(v.z, a2v, c2v), 0.f);
        v.w = fmaxf(fmaf(v.w, a3, c3), 0.f);
        ((float4*)(out + (size_t)r * D))[lane] = v;
    }
}

// ---------------- launch ----------------
extern "C" void kernel_launch(void* const* d_in, const int* in_sizes, int n_in,
                              void* d_out, int out_size) {
    const float* x    = (const float*)d_in[0];
    const int*   ei   = (const int*)d_in[1];   // int64 in reference -> delivered int32
    const float* Wm   = (const float*)d_in[2];
    // d_in[3] = b_mlp  : cancels inside training-mode BatchNorm
    const float* gam1 = (const float*)d_in[4];
    const float* bet1 = (const float*)d_in[5];
    const float* Wc   = (const float*)d_in[6];
    // d_in[7] = b_conv : cancels inside training-mode BatchNorm
    const float* gam2 = (const float*)d_in[8];
    const float* bet2 = (const float*)d_in[9];
    float* out = (float*)d_out;

    const int N = in_sizes[0] / D;
    const int E = in_sizes[1] / 2;
    const int* srcp = ei;
    const int* dstp = ei + E;
    const float invN = 1.0f / (float)N;
    const int nchunks = (N + 511) / 512;
    const int EB = (E + 255) / 256;
    const int GB = (N + 127) / 128;

    k_pack<<<64, 256>>>(Wm, Wc, N);                       // + all state resets
    k_g0<<<GB + EB, 256>>>(x, dstp, E, N, GB);            // gemm0 + deg
    k_cs0s1<<<256 + nchunks, 256>>>(N, gam1, bet1, invN, nchunks);  // colstats0 + full scan
    k_g1f<<<GB + EB, 256>>>(srcp, dstp, E, N, GB);        // gemm1 + fill (independent)
    k_gather<<<(N * 32 + 255) / 256, 256>>>(N);
    k_cf<<<256, 256>>>(out, N, gam2, bet2, invN, 256);    // colstats1+affine+final
}